// round 1
// baseline (speedup 1.0000x reference)
#include <cuda_runtime.h>
#include <math.h>

// Problem constants
#define BB 32
#define NN 1024
#define HH 256
#define AA 32
#define OO 256
#define MM (BB*NN)   // 32768 particle rows

// ---------------- scratch (static device arrays; no allocation) -------------
__device__ float g_XR[MM*HH];      // particles * reset   (cols 0..255 of x_reset)
__device__ float g_U [MM*HH];      // update gate
__device__ float g_NXT[MM*HH];     // nxt (pre-resample copy; gather source)
__device__ float g_Z1[MM*HH];      // first MLP hidden
__device__ float g_llpart[2*MM];   // per-half partial log_lik dot (deterministic, no atomics)
__device__ int   g_idx[MM];        // final gather index (resample idx or identity)
__device__ float g_partial[BB*128*HH]; // belief partial sums

__device__ __forceinline__ float sigmoid_f(float x){ return 1.0f/(1.0f+expf(-x)); }
__device__ __forceinline__ float gelu_f(float x){ return 0.5f*x*(1.0f+erff(x*0.70710678118654752f)); }

// ---------------------------------------------------------------------------
// Generic fused GEMM: C[M x Ncols] = A[M x K] @ W[K x Ncols] with mode-specific
// A gather (concat inputs on the fly) and fused epilogue.
//   MODE 1: A=[particles|action] K=288, W=[Wr|Wu] (Ncols=512).
//           epilogue: n<256 -> XR = p*sigmoid(+br);  n>=256 -> U = sigmoid(+bu)
//   MODE 2: A=[XR|action] K=288, W=Wc. epilogue: nxt=(1-u)*p + u*tanh(+bc)
//   MODE 3: A=[NXT|obs] K=512, W=W0. epilogue: Z1 = gelu(+b0)
//   MODE 4: A=Z1 K=256, W=W1. epilogue: llpart = sum_n gelu(+b1)*W2[n]
// Tile: 128x128x8, 256 threads, 8x8 microtile per thread.
// ---------------------------------------------------------------------------
template<int MODE>
__global__ void __launch_bounds__(256) gemm_k(
    const float* __restrict__ particles,
    const float* __restrict__ action,
    const float* __restrict__ observation,
    const float* __restrict__ Wr, const float* __restrict__ br,
    const float* __restrict__ Wu, const float* __restrict__ bu,
    const float* __restrict__ Wc, const float* __restrict__ bc,
    const float* __restrict__ W0, const float* __restrict__ b0,
    const float* __restrict__ W1, const float* __restrict__ b1,
    const float* __restrict__ W2)
{
    constexpr int K = (MODE==1||MODE==2) ? 288 : (MODE==3 ? 512 : 256);

    __shared__ float As[8][128];
    __shared__ float Bs[8][128];

    const int tid  = threadIdx.x;
    const int m0   = blockIdx.y * 128;
    const int n0   = blockIdx.x * 128;
    const int bidx = m0 >> 10;                 // batch index (block never straddles batches)
    const int trow = (tid >> 4) << 3;          // 0..120
    const int tcol = (tid & 15) << 3;          // 0..120

    const float* Wbase;
    if      (MODE==1) Wbase = (n0 < 256) ? Wr : Wu;
    else if (MODE==2) Wbase = Wc;
    else if (MODE==3) Wbase = W0;
    else              Wbase = W1;
    const int nw0 = (MODE==1 && n0 >= 256) ? (n0 - 256) : n0;   // col offset within selected W

    float acc[8][8];
#pragma unroll
    for (int i=0;i<8;i++)
#pragma unroll
        for (int j=0;j<8;j++) acc[i][j]=0.f;

    const int e0   = tid * 4;
    const int la_m = e0 >> 3;        // 0..127
    const int la_k = e0 & 7;         // 0 or 4
    const int lb_k = e0 >> 7;        // 0..7
    const int lb_n = e0 & 127;       // multiple of 4

    for (int k0 = 0; k0 < K; k0 += 8) {
        // ---- stage A tile (concat gather; float4 chunks never straddle 256) ----
        {
            const int k = k0 + la_k;
            const int m = m0 + la_m;
            float4 av;
            if (MODE==1) {
                av = (k < 256) ? *(const float4*)(particles + m*HH + k)
                               : *(const float4*)(action + bidx*AA + (k-256));
            } else if (MODE==2) {
                av = (k < 256) ? *(const float4*)(g_XR + m*HH + k)
                               : *(const float4*)(action + bidx*AA + (k-256));
            } else if (MODE==3) {
                av = (k < 256) ? *(const float4*)(g_NXT + m*HH + k)
                               : *(const float4*)(observation + bidx*OO + (k-256));
            } else {
                av = *(const float4*)(g_Z1 + m*HH + k);
            }
            As[la_k+0][la_m]=av.x; As[la_k+1][la_m]=av.y;
            As[la_k+2][la_m]=av.z; As[la_k+3][la_m]=av.w;
        }
        // ---- stage W tile ----
        {
            const int k = k0 + lb_k;
            float4 bv = *(const float4*)(Wbase + k*HH + nw0 + lb_n);
            *(float4*)&Bs[lb_k][lb_n] = bv;
        }
        __syncthreads();

#pragma unroll
        for (int kk=0; kk<8; kk++) {
            float4 av0 = *(const float4*)&As[kk][trow];
            float4 av1 = *(const float4*)&As[kk][trow+4];
            float4 bv0 = *(const float4*)&Bs[kk][tcol];
            float4 bv1 = *(const float4*)&Bs[kk][tcol+4];
            float ar[8] = {av0.x,av0.y,av0.z,av0.w,av1.x,av1.y,av1.z,av1.w};
            float brg[8] = {bv0.x,bv0.y,bv0.z,bv0.w,bv1.x,bv1.y,bv1.z,bv1.w};
#pragma unroll
            for (int i=0;i<8;i++)
#pragma unroll
                for (int j=0;j<8;j++)
                    acc[i][j] = fmaf(ar[i], brg[j], acc[i][j]);
        }
        __syncthreads();
    }

    // ---------------- fused epilogues ----------------
    if (MODE==1) {
        const bool isR = (n0 < 256);
        const float* bias = isR ? br : bu;
#pragma unroll
        for (int i=0;i<8;i++) {
            const int m = m0 + trow + i;
#pragma unroll
            for (int j=0;j<8;j++) {
                const int n = nw0 + tcol + j;
                float s = sigmoid_f(acc[i][j] + bias[n]);
                if (isR) g_XR[m*HH+n] = particles[m*HH+n] * s;
                else     g_U [m*HH+n] = s;
            }
        }
    } else if (MODE==2) {
#pragma unroll
        for (int i=0;i<8;i++) {
            const int m = m0 + trow + i;
#pragma unroll
            for (int j=0;j<8;j++) {
                const int n = nw0 + tcol + j;
                float c = tanhf(acc[i][j] + bc[n]);
                float u = g_U[m*HH+n];
                float p = particles[m*HH+n];
                g_NXT[m*HH+n] = (1.0f - u)*p + u*c;
            }
        }
    } else if (MODE==3) {
#pragma unroll
        for (int i=0;i<8;i++) {
            const int m = m0 + trow + i;
#pragma unroll
            for (int j=0;j<8;j++) {
                const int n = nw0 + tcol + j;
                g_Z1[m*HH+n] = gelu_f(acc[i][j] + b0[n]);
            }
        }
    } else { // MODE 4: fused z2 = gelu(.+b1); partial log_lik = sum_n z2*W2[n]
        __shared__ float red[128][17];
        const int cg = tid & 15;
#pragma unroll
        for (int i=0;i<8;i++) {
            float s = 0.f;
#pragma unroll
            for (int j=0;j<8;j++) {
                const int n = nw0 + tcol + j;
                float z = gelu_f(acc[i][j] + b1[n]);
                s += z * W2[n];
            }
            red[trow+i][cg] = s;
        }
        __syncthreads();
        if (tid < 128) {
            float s = 0.f;
#pragma unroll
            for (int c=0;c<16;c++) s += red[tid][c];   // fixed order -> deterministic
            g_llpart[(n0 >> 7)*MM + m0 + tid] = s;
        }
    }
}

// ---------------------------------------------------------------------------
// Per-batch weight update: softmax, ESS, systematic resampling index, outputs.
// One block per batch row, 1024 threads (one per particle).
// ---------------------------------------------------------------------------
__global__ void __launch_bounds__(NN) stage_weights_k(
    const float* __restrict__ weights,
    const float* __restrict__ uin,
    const float* __restrict__ b2,
    float* __restrict__ dout)
{
    __shared__ float sh[NN];
    const int b = blockIdx.x;
    const int n = threadIdx.x;
    const int m = b*NN + n;

    const float ll = g_llpart[m] + g_llpart[MM + m] + b2[0];
    const float lw = logf(weights[m] + 1e-10f) + ll;

    // max reduce
    sh[n] = lw; __syncthreads();
    for (int s=512; s>0; s>>=1) { if (n<s) sh[n] = fmaxf(sh[n], sh[n+s]); __syncthreads(); }
    const float mx = sh[0]; __syncthreads();

    // sum of exp
    const float e = expf(lw - mx);
    sh[n] = e; __syncthreads();
    for (int s=512; s>0; s>>=1) { if (n<s) sh[n] += sh[n+s]; __syncthreads(); }
    const float S = sh[0]; __syncthreads();
    const float nw = e / S;

    // ESS
    sh[n] = nw*nw; __syncthreads();
    for (int s=512; s>0; s>>=1) { if (n<s) sh[n] += sh[n+s]; __syncthreads(); }
    const float ess = 1.0f / (sh[0] + 1e-10f); __syncthreads();
    const bool should = ess < 0.5f * (float)NN;

    // inclusive scan (Hillis-Steele) -> cumsum in sh
    float val = nw;
    sh[n] = val; __syncthreads();
    for (int off=1; off<NN; off<<=1) {
        float add = (n>=off) ? sh[n-off] : 0.f;
        __syncthreads();
        val += add;
        sh[n] = val;
        __syncthreads();
    }

    // systematic resampling position + lower_bound searchsorted
    float pos = uin[b]*(1.0f/(float)NN) + (float)n*(1.0f/(float)NN);
    pos = fminf(pos, 0.9999f);
    int lo = 0, hi = NN;
    while (lo < hi) {
        int mid = (lo + hi) >> 1;
        if (sh[mid] < pos) lo = mid + 1; else hi = mid;
    }
    int idx = lo < (NN-1) ? lo : (NN-1);

    g_idx[m] = should ? idx : n;
    const float wf = should ? (1.0f/(float)NN) : nw;
    dout[8192 + (size_t)MM*HH + m] = wf;                   // new_w
    if (n == 0) dout[8192 + (size_t)MM*HH + MM + b] = ess; // ess
}

// ---------------------------------------------------------------------------
// Gather final nxt rows (resampled or identity) into d_out + belief partials.
// grid (128 chunks, B), 256 threads (one per h).
// ---------------------------------------------------------------------------
__global__ void __launch_bounds__(HH) gather_belief_k(float* __restrict__ dout)
{
    const int b = blockIdx.y;
    const int chunk = blockIdx.x;
    const int h = threadIdx.x;
    const float* dw = dout + 8192 + (size_t)MM*HH;
    float* dnxt = dout + 8192;

    float accp = 0.f;
#pragma unroll
    for (int r=0; r<8; r++) {
        const int j = chunk*8 + r;
        const int src = g_idx[b*NN + j];
        const float v = g_NXT[(size_t)(b*NN + src)*HH + h];
        dnxt[(size_t)(b*NN + j)*HH + h] = v;
        accp = fmaf(v, dw[b*NN + j], accp);
    }
    g_partial[(b*128 + chunk)*HH + h] = accp;
}

__global__ void __launch_bounds__(HH) belief_reduce_k(float* __restrict__ dout)
{
    const int b = blockIdx.x;
    const int h = threadIdx.x;
    float s = 0.f;
    for (int c=0; c<128; c++) s += g_partial[(b*128 + c)*HH + h];
    dout[b*HH + h] = s;   // belief
}

// ---------------------------------------------------------------------------
extern "C" void kernel_launch(void* const* d_in, const int* in_sizes, int n_in,
                              void* d_out, int out_size)
{
    (void)in_sizes; (void)n_in; (void)out_size;
    const float* particles   = (const float*)d_in[0];
    const float* weights     = (const float*)d_in[1];
    const float* action      = (const float*)d_in[2];
    const float* observation = (const float*)d_in[3];
    const float* uin         = (const float*)d_in[4];
    const float* Wr = (const float*)d_in[5];  const float* br = (const float*)d_in[6];
    const float* Wu = (const float*)d_in[7];  const float* bu = (const float*)d_in[8];
    const float* Wc = (const float*)d_in[9];  const float* bc = (const float*)d_in[10];
    const float* W0 = (const float*)d_in[11]; const float* b0 = (const float*)d_in[12];
    const float* W1 = (const float*)d_in[13]; const float* b1 = (const float*)d_in[14];
    const float* W2 = (const float*)d_in[15]; const float* b2 = (const float*)d_in[16];
    float* out = (float*)d_out;

    const dim3 blk(256);
    // G1: reset+update gates (N=512 combined)
    gemm_k<1><<<dim3(4, MM/128), blk>>>(particles, action, observation,
        Wr,br,Wu,bu,Wc,bc,W0,b0,W1,b1,W2);
    // G2: candidate + nxt
    gemm_k<2><<<dim3(2, MM/128), blk>>>(particles, action, observation,
        Wr,br,Wu,bu,Wc,bc,W0,b0,W1,b1,W2);
    // G3: first MLP layer
    gemm_k<3><<<dim3(2, MM/128), blk>>>(particles, action, observation,
        Wr,br,Wu,bu,Wc,bc,W0,b0,W1,b1,W2);
    // G4: second MLP layer + fused log_lik dot
    gemm_k<4><<<dim3(2, MM/128), blk>>>(particles, action, observation,
        Wr,br,Wu,bu,Wc,bc,W0,b0,W1,b1,W2);
    // per-batch softmax / ESS / resample indices
    stage_weights_k<<<BB, NN>>>(weights, uin, b2, out);
    // gather + belief partials
    gather_belief_k<<<dim3(128, BB), HH>>>(out);
    // belief final reduce
    belief_reduce_k<<<BB, HH>>>(out);
}

// round 3
// speedup vs baseline: 2.1527x; 2.1527x over previous
#include <cuda_runtime.h>
#include <cuda_bf16.h>
#include <cstdint>
#include <math.h>

#define BB 32
#define NN 1024
#define HH 256
#define AA 32
#define OO 256
#define MM (BB*NN)   // 32768 particle rows

// ---------------- scratch (static device arrays; no allocation) -------------
__device__ float g_XR[MM*HH];      // particles * reset
__device__ float g_U [MM*HH];      // update gate
__device__ float g_NXT[MM*HH];     // nxt (pre-resample; gather source)
__device__ float g_Z1[MM*HH];      // first MLP hidden
__device__ float g_llpart[2*MM];   // per-half log_lik partials
__device__ int   g_idx[MM];        // gather index
__device__ float g_partial[BB*128*HH];

// transposed + bf16 hi/lo split weights: WrT | WuT | WcT | W0T | W1T  ([n][k])
#define WT_TOTAL 417792
__device__ __nv_bfloat16 g_WT_hi[WT_TOTAL];
__device__ __nv_bfloat16 g_WT_lo[WT_TOTAL];
// offsets: Wr 0, Wu 73728, Wc 147456, W0 221184, W1 352256

__device__ __forceinline__ float sigmoid_f(float x){ return 1.0f/(1.0f+expf(-x)); }
__device__ __forceinline__ float gelu_f(float x){ return 0.5f*x*(1.0f+erff(x*0.70710678118654752f)); }

// fp32 -> (hi,lo) bf16 split, packed pairs (element k in low 16 bits)
__device__ __forceinline__ void split2(float x, float y, uint32_t& hi, uint32_t& lo){
    __nv_bfloat16 hx = __float2bfloat16_rn(x), hy = __float2bfloat16_rn(y);
    __nv_bfloat16 lx = __float2bfloat16_rn(x - __bfloat162float(hx));
    __nv_bfloat16 ly = __float2bfloat16_rn(y - __bfloat162float(hy));
    hi = (uint32_t)__bfloat16_as_ushort(hx) | ((uint32_t)__bfloat16_as_ushort(hy) << 16);
    lo = (uint32_t)__bfloat16_as_ushort(lx) | ((uint32_t)__bfloat16_as_ushort(ly) << 16);
}

__device__ __forceinline__ void mma16816(float* c, const uint32_t* a, uint32_t b0, uint32_t b1){
    asm volatile("mma.sync.aligned.m16n8k16.row.col.f32.bf16.bf16.f32 "
        "{%0,%1,%2,%3}, {%4,%5,%6,%7}, {%8,%9}, {%0,%1,%2,%3};"
        : "+f"(c[0]), "+f"(c[1]), "+f"(c[2]), "+f"(c[3])
        : "r"(a[0]), "r"(a[1]), "r"(a[2]), "r"(a[3]), "r"(b0), "r"(b1));
}

// ---------------------------------------------------------------------------
// Weight prep: transpose W[K][256] -> WT[n][k], split fp32 -> bf16 hi/lo.
// grid (16, 8, 5), block (32, 8)
// ---------------------------------------------------------------------------
__global__ void wprep_k(const float* __restrict__ Wr, const float* __restrict__ Wu,
                        const float* __restrict__ Wc, const float* __restrict__ W0,
                        const float* __restrict__ W1)
{
    const int mid = blockIdx.z;
    const int Ks[5] = {288,288,288,512,256};
    const size_t offs[5] = {0,73728,147456,221184,352256};
    const float* src = (mid==0)?Wr:(mid==1)?Wu:(mid==2)?Wc:(mid==3)?W0:W1;
    const int K = Ks[mid];
    const int k0 = blockIdx.x * 32;
    if (k0 >= K) return;
    const int n0 = blockIdx.y * 32;
    const int tx = threadIdx.x, ty = threadIdx.y;

    __shared__ float tile[32][33];
#pragma unroll
    for (int i=0;i<4;i++)
        tile[ty*4+i][tx] = src[(size_t)(k0+ty*4+i)*HH + n0 + tx];
    __syncthreads();
#pragma unroll
    for (int i=0;i<4;i++){
        const int r = ty*4+i;
        const float v = tile[tx][r];
        __nv_bfloat16 h = __float2bfloat16_rn(v);
        __nv_bfloat16 l = __float2bfloat16_rn(v - __bfloat162float(h));
        const size_t o = offs[mid] + (size_t)(n0+r)*K + k0 + tx;
        g_WT_hi[o] = h;
        g_WT_lo[o] = l;
    }
}

// ---------------------------------------------------------------------------
// HMMA GEMM: C[128 x 128] per CTA = A[128 x K] @ W[K x 128-slice]
// MODE 1: A=[particles|action] K=288, x<2 -> Wr (XR epi), x>=2 -> Wu (U epi)
// MODE 2: A=[XR|action] K=288, Wc; nxt = (1-u)p + u*tanh
// MODE 3: A=[NXT|obs]  K=512, W0; Z1 = gelu
// MODE 4: A=Z1         K=256, W1; llpart = sum_n gelu(.+b1)*W2[n]
// 256 threads = 8 warps (4M x 2N), warp tile 32x64, bf16 3-term hi/lo split.
// ---------------------------------------------------------------------------
template<int MODE>
__global__ void __launch_bounds__(256, 2) hmma_gemm_k(
    const float* __restrict__ particles, const float* __restrict__ action,
    const float* __restrict__ observation,
    const float* __restrict__ br, const float* __restrict__ bu,
    const float* __restrict__ bc, const float* __restrict__ b0,
    const float* __restrict__ b1, const float* __restrict__ W2)
{
    constexpr int K = (MODE==1 || MODE==2) ? 288 : (MODE==3 ? 512 : 256);
    constexpr int P = K / 32;

    // padded rows: 40 bf16 = 80 bytes (conflict-free fragment loads)
    __shared__ __align__(16) char sAhi[128*80];
    __shared__ __align__(16) char sAlo[128*80];
    __shared__ __align__(16) char sBhi[128*80];
    __shared__ __align__(16) char sBlo[128*80];
    __shared__ float red[128][2];

    const int tid  = threadIdx.x;
    const int wid  = tid >> 5;
    const int lane = tid & 31;
    const int g    = lane >> 2;
    const int tig  = lane & 3;
    const int warpM = wid >> 1;       // 0..3
    const int warpN = wid & 1;        // 0..1
    const int m0   = blockIdx.y * 128;
    const int bidx = blockIdx.y >> 3; // batch

    // weight slice
    size_t wt_off; int nw0;
    if (MODE==1){ wt_off = (blockIdx.x < 2) ? 0 : 73728; nw0 = (blockIdx.x & 1) * 128; }
    else if (MODE==2){ wt_off = 147456; nw0 = blockIdx.x * 128; }
    else if (MODE==3){ wt_off = 221184; nw0 = blockIdx.x * 128; }
    else             { wt_off = 352256; nw0 = blockIdx.x * 128; }

    const float* Asrc = (MODE==1) ? particles : (MODE==2) ? g_XR : (MODE==3) ? g_NXT : g_Z1;
    const float* tail = (MODE==3) ? (observation + bidx*OO) : (action + bidx*AA);

    float acc[2][8][4];
#pragma unroll
    for (int i=0;i<2;i++)
#pragma unroll
        for (int j=0;j<8;j++)
#pragma unroll
            for (int q=0;q<4;q++) acc[i][j][q] = 0.f;

    // staging maps
    const int rA = tid >> 1, hA = tid & 1;       // A: row rA, k-half hA*16
    const float* arow = Asrc + (size_t)(m0 + rA) * HH;
    const int nB = tid >> 1, hB = tid & 1;       // B: row nB, 16 bf16 half
    const __nv_bfloat16* wrow_hi = g_WT_hi + wt_off + (size_t)(nw0 + nB) * K;
    const __nv_bfloat16* wrow_lo = g_WT_lo + wt_off + (size_t)(nw0 + nB) * K;

#pragma unroll 1
    for (int p = 0; p < P; ++p){
        const int k0 = p * 32;
        if (p) __syncthreads();   // protect smem reuse

        // ---- stage A (fp32 -> hi/lo bf16) ----
#pragma unroll
        for (int q = 0; q < 4; ++q){
            const int kl = hA*16 + q*4;
            const int k  = k0 + kl;
            float4 v;
            if (MODE==4 || k < 256)  v = *(const float4*)(arow + k);
            else                     v = *(const float4*)(tail + (k - 256));
            uint32_t h0,l0,h1,l1;
            split2(v.x, v.y, h0, l0);
            split2(v.z, v.w, h1, l1);
            *(uint2*)(sAhi + rA*80 + kl*2) = make_uint2(h0, h1);
            *(uint2*)(sAlo + rA*80 + kl*2) = make_uint2(l0, l1);
        }
        // ---- stage B (pre-split bf16, direct 16B copies) ----
        {
            const __nv_bfloat16* sh_ = wrow_hi + k0 + hB*16;
            const __nv_bfloat16* sl_ = wrow_lo + k0 + hB*16;
            *(uint4*)(sBhi + nB*80 + hB*32)      = *(const uint4*)(sh_);
            *(uint4*)(sBhi + nB*80 + hB*32 + 16) = *(const uint4*)(sh_ + 8);
            *(uint4*)(sBlo + nB*80 + hB*32)      = *(const uint4*)(sl_);
            *(uint4*)(sBlo + nB*80 + hB*32 + 16) = *(const uint4*)(sl_ + 8);
        }
        __syncthreads();

        // ---- compute: 2 k16 steps ----
#pragma unroll
        for (int ks = 0; ks < 2; ++ks){
            const int kk = ks*16;
            uint32_t ah[2][4], al[2][4];
#pragma unroll
            for (int mf = 0; mf < 2; ++mf){
                const int mr = warpM*32 + mf*16;
                const int cA = (kk + tig*2)*2;
                ah[mf][0] = *(const uint32_t*)(sAhi + (mr+g  )*80 + cA);
                ah[mf][1] = *(const uint32_t*)(sAhi + (mr+g+8)*80 + cA);
                ah[mf][2] = *(const uint32_t*)(sAhi + (mr+g  )*80 + cA + 16);
                ah[mf][3] = *(const uint32_t*)(sAhi + (mr+g+8)*80 + cA + 16);
                al[mf][0] = *(const uint32_t*)(sAlo + (mr+g  )*80 + cA);
                al[mf][1] = *(const uint32_t*)(sAlo + (mr+g+8)*80 + cA);
                al[mf][2] = *(const uint32_t*)(sAlo + (mr+g  )*80 + cA + 16);
                al[mf][3] = *(const uint32_t*)(sAlo + (mr+g+8)*80 + cA + 16);
            }
#pragma unroll
            for (int nf = 0; nf < 8; ++nf){
                const int nr = warpN*64 + nf*8 + g;
                const int cB = (kk + tig*2)*2;
                const uint32_t bh0 = *(const uint32_t*)(sBhi + nr*80 + cB);
                const uint32_t bh1 = *(const uint32_t*)(sBhi + nr*80 + cB + 16);
                const uint32_t bl0 = *(const uint32_t*)(sBlo + nr*80 + cB);
                const uint32_t bl1 = *(const uint32_t*)(sBlo + nr*80 + cB + 16);
#pragma unroll
                for (int mf = 0; mf < 2; ++mf){
                    mma16816(acc[mf][nf], ah[mf], bh0, bh1);
                    mma16816(acc[mf][nf], ah[mf], bl0, bl1);
                    mma16816(acc[mf][nf], al[mf], bh0, bh1);
                }
            }
        }
    }

    // ---------------- epilogue ----------------
    if (MODE == 4){
        float pr[2][2] = {{0.f,0.f},{0.f,0.f}};   // [mf][row g / g+8]
#pragma unroll
        for (int mf=0; mf<2; ++mf){
#pragma unroll
            for (int nf=0; nf<8; ++nf){
                const int nc = nw0 + warpN*64 + nf*8 + tig*2;
                const float2 bv = *(const float2*)(b1 + nc);
                const float2 wv = *(const float2*)(W2 + nc);
                float* c = acc[mf][nf];
                pr[mf][0] += gelu_f(c[0]+bv.x)*wv.x + gelu_f(c[1]+bv.y)*wv.y;
                pr[mf][1] += gelu_f(c[2]+bv.x)*wv.x + gelu_f(c[3]+bv.y)*wv.y;
            }
        }
#pragma unroll
        for (int mf=0; mf<2; ++mf)
#pragma unroll
            for (int rr=0; rr<2; ++rr){
                float v = pr[mf][rr];
                v += __shfl_xor_sync(0xffffffffu, v, 1);
                v += __shfl_xor_sync(0xffffffffu, v, 2);
                if (tig == 0) red[warpM*32 + mf*16 + rr*8 + g][warpN] = v;
            }
        __syncthreads();
        if (tid < 128)
            g_llpart[(size_t)blockIdx.x*MM + m0 + tid] = red[tid][0] + red[tid][1];
        return;
    }

    float* dest; const float* bias;
    if (MODE==1){ dest = (blockIdx.x<2) ? g_XR : g_U; bias = (blockIdx.x<2) ? br : bu; }
    else if (MODE==2){ dest = g_NXT; bias = bc; }
    else { dest = g_Z1; bias = b0; }
    const bool isR = (MODE==1) && (blockIdx.x < 2);

#pragma unroll
    for (int mf=0; mf<2; ++mf){
#pragma unroll
        for (int nf=0; nf<8; ++nf){
            const int nc = nw0 + warpN*64 + nf*8 + tig*2;
            const int m1_ = m0 + warpM*32 + mf*16 + g;
            const int m2_ = m1_ + 8;
            const float2 bv = *(const float2*)(bias + nc);
            float* c = acc[mf][nf];
            float2 r1, r2;
            if (MODE==1){
                const float s0 = sigmoid_f(c[0]+bv.x), s1 = sigmoid_f(c[1]+bv.y);
                const float s2 = sigmoid_f(c[2]+bv.x), s3 = sigmoid_f(c[3]+bv.y);
                if (isR){
                    const float2 p1 = *(const float2*)(particles + (size_t)m1_*HH + nc);
                    const float2 p2 = *(const float2*)(particles + (size_t)m2_*HH + nc);
                    r1 = make_float2(p1.x*s0, p1.y*s1);
                    r2 = make_float2(p2.x*s2, p2.y*s3);
                } else {
                    r1 = make_float2(s0, s1);
                    r2 = make_float2(s2, s3);
                }
            } else if (MODE==2){
                const float2 u1 = *(const float2*)(g_U + (size_t)m1_*HH + nc);
                const float2 u2 = *(const float2*)(g_U + (size_t)m2_*HH + nc);
                const float2 p1 = *(const float2*)(particles + (size_t)m1_*HH + nc);
                const float2 p2 = *(const float2*)(particles + (size_t)m2_*HH + nc);
                r1.x = (1.f-u1.x)*p1.x + u1.x*tanhf(c[0]+bv.x);
                r1.y = (1.f-u1.y)*p1.y + u1.y*tanhf(c[1]+bv.y);
                r2.x = (1.f-u2.x)*p2.x + u2.x*tanhf(c[2]+bv.x);
                r2.y = (1.f-u2.y)*p2.y + u2.y*tanhf(c[3]+bv.y);
            } else {
                r1 = make_float2(gelu_f(c[0]+bv.x), gelu_f(c[1]+bv.y));
                r2 = make_float2(gelu_f(c[2]+bv.x), gelu_f(c[3]+bv.y));
            }
            *(float2*)(dest + (size_t)m1_*HH + nc) = r1;
            *(float2*)(dest + (size_t)m2_*HH + nc) = r2;
        }
    }
}

// ---------------------------------------------------------------------------
// Per-batch weight update: softmax, ESS, systematic resampling index, outputs.
// ---------------------------------------------------------------------------
__global__ void __launch_bounds__(NN) stage_weights_k(
    const float* __restrict__ weights,
    const float* __restrict__ uin,
    const float* __restrict__ b2,
    float* __restrict__ dout)
{
    __shared__ float sh[NN];
    const int b = blockIdx.x;
    const int n = threadIdx.x;
    const int m = b*NN + n;

    const float ll = g_llpart[m] + g_llpart[MM + m] + b2[0];
    const float lw = logf(weights[m] + 1e-10f) + ll;

    sh[n] = lw; __syncthreads();
    for (int s=512; s>0; s>>=1) { if (n<s) sh[n] = fmaxf(sh[n], sh[n+s]); __syncthreads(); }
    const float mx = sh[0]; __syncthreads();

    const float e = expf(lw - mx);
    sh[n] = e; __syncthreads();
    for (int s=512; s>0; s>>=1) { if (n<s) sh[n] += sh[n+s]; __syncthreads(); }
    const float S = sh[0]; __syncthreads();
    const float nw = e / S;

    sh[n] = nw*nw; __syncthreads();
    for (int s=512; s>0; s>>=1) { if (n<s) sh[n] += sh[n+s]; __syncthreads(); }
    const float ess = 1.0f / (sh[0] + 1e-10f); __syncthreads();
    const bool should = ess < 0.5f * (float)NN;

    float val = nw;
    sh[n] = val; __syncthreads();
    for (int off=1; off<NN; off<<=1) {
        float add = (n>=off) ? sh[n-off] : 0.f;
        __syncthreads();
        val += add;
        sh[n] = val;
        __syncthreads();
    }

    float pos = uin[b]*(1.0f/(float)NN) + (float)n*(1.0f/(float)NN);
    pos = fminf(pos, 0.9999f);
    int lo = 0, hi = NN;
    while (lo < hi) {
        int mid = (lo + hi) >> 1;
        if (sh[mid] < pos) lo = mid + 1; else hi = mid;
    }
    int idx = lo < (NN-1) ? lo : (NN-1);

    g_idx[m] = should ? idx : n;
    const float wf = should ? (1.0f/(float)NN) : nw;
    dout[8192 + (size_t)MM*HH + m] = wf;
    if (n == 0) dout[8192 + (size_t)MM*HH + MM + b] = ess;
}

__global__ void __launch_bounds__(HH) gather_belief_k(float* __restrict__ dout)
{
    const int b = blockIdx.y;
    const int chunk = blockIdx.x;
    const int h = threadIdx.x;
    const float* dw = dout + 8192 + (size_t)MM*HH;
    float* dnxt = dout + 8192;

    float accp = 0.f;
#pragma unroll
    for (int r=0; r<8; r++) {
        const int j = chunk*8 + r;
        const int src = g_idx[b*NN + j];
        const float v = g_NXT[(size_t)(b*NN + src)*HH + h];
        dnxt[(size_t)(b*NN + j)*HH + h] = v;
        accp = fmaf(v, dw[b*NN + j], accp);
    }
    g_partial[(b*128 + chunk)*HH + h] = accp;
}

__global__ void __launch_bounds__(HH) belief_reduce_k(float* __restrict__ dout)
{
    const int b = blockIdx.x;
    const int h = threadIdx.x;
    float s = 0.f;
    for (int c=0; c<128; c++) s += g_partial[(b*128 + c)*HH + h];
    dout[b*HH + h] = s;
}

// ---------------------------------------------------------------------------
extern "C" void kernel_launch(void* const* d_in, const int* in_sizes, int n_in,
                              void* d_out, int out_size)
{
    (void)in_sizes; (void)n_in; (void)out_size;
    const float* particles   = (const float*)d_in[0];
    const float* weights     = (const float*)d_in[1];
    const float* action      = (const float*)d_in[2];
    const float* observation = (const float*)d_in[3];
    const float* uin         = (const float*)d_in[4];
    const float* Wr = (const float*)d_in[5];  const float* br = (const float*)d_in[6];
    const float* Wu = (const float*)d_in[7];  const float* bu = (const float*)d_in[8];
    const float* Wc = (const float*)d_in[9];  const float* bc = (const float*)d_in[10];
    const float* W0 = (const float*)d_in[11]; const float* b0 = (const float*)d_in[12];
    const float* W1 = (const float*)d_in[13]; const float* b1 = (const float*)d_in[14];
    const float* W2 = (const float*)d_in[15]; const float* b2 = (const float*)d_in[16];
    float* out = (float*)d_out;

    // weight transpose + bf16 split (tiny)
    wprep_k<<<dim3(16, 8, 5), dim3(32, 8)>>>(Wr, Wu, Wc, W0, W1);

    const dim3 blk(256);
    hmma_gemm_k<1><<<dim3(4, MM/128), blk>>>(particles, action, observation,
        br, bu, bc, b0, b1, W2);
    hmma_gemm_k<2><<<dim3(2, MM/128), blk>>>(particles, action, observation,
        br, bu, bc, b0, b1, W2);
    hmma_gemm_k<3><<<dim3(2, MM/128), blk>>>(particles, action, observation,
        br, bu, bc, b0, b1, W2);
    hmma_gemm_k<4><<<dim3(2, MM/128), blk>>>(particles, action, observation,
        br, bu, bc, b0, b1, W2);
    stage_weights_k<<<BB, NN>>>(weights, uin, b2, out);
    gather_belief_k<<<dim3(128, BB), HH>>>(out);
    belief_reduce_k<<<BB, HH>>>(out);
}